// round 16
// baseline (speedup 1.0000x reference)
#include <cuda_runtime.h>
#include <cuda_fp16.h>

#define BM 128    // m cols per block
#define DD 64
#define NDC 8     // double-chunks (8 dims = 16B)
#define THREADS 512
#define BNB 128   // big tile rows

struct __align__(16) h2quad { __half2 a, b, c, d; };

__device__ __forceinline__ void ffma_acc1(float &acc, float v) {
    asm("fma.rn.f32 %0, %1, 0f3F800000, %0;" : "+f"(acc) : "f"(v));
}

__device__ __forceinline__ float sum8(const h2quad &q) {
    float2 fa = __half22float2(q.a), fb = __half22float2(q.b);
    float2 fc = __half22float2(q.c), fd = __half22float2(q.d);
    return ((fa.x + fa.y) + (fb.x + fb.y)) + ((fc.x + fc.y) + (fd.x + fd.y));
}

__device__ __forceinline__ h2quad cvt2(const float4 &v0, const float4 &v1) {
    h2quad q;
    q.a = __floats2half2_rn(v0.x, v0.y);
    q.b = __floats2half2_rn(v0.z, v0.w);
    q.c = __floats2half2_rn(v1.x, v1.y);
    q.d = __floats2half2_rn(v1.z, v1.w);
    return q;
}

__global__ __launch_bounds__(THREADS, 1)
void cdist_l1_kernel(const float4* __restrict__ x4,
                     const float4* __restrict__ w4,
                     float* __restrict__ out,
                     int Mtot, int nbig)
{
    __shared__ h2quad xs[NDC][BNB];   // 16KB (xr reads are warp-uniform -> no pad)
    __shared__ h2quad ws[NDC][BM];    // 16KB
    __shared__ float Sxp[4][BNB];     // partial row sums
    __shared__ float Swp[4][BM];

    const int tid = threadIdx.x;
    const int m0 = blockIdx.x * BM;
    const int tx = tid & 31;   // m: j*32 + tx
    const int ty = tid >> 5;   // n: ty*8 + i (big) / ty*4 + i (small)

    // ---- w tile: 128 rows x 8 dc = 1024 items, 2/thread ----
    {
        const int m = tid & 127;
        const int w = tid >> 7;          // 0..3
        float pw = 0.f;
        #pragma unroll
        for (int i = 0; i < 2; i++) {
            int dc = w + 4 * i;
            float4 v0 = w4[(size_t)(m0 + m) * 16 + dc * 2];
            float4 v1 = w4[(size_t)(m0 + m) * 16 + dc * 2 + 1];
            h2quad q = cvt2(v0, v1);
            ws[dc][m] = q;
            pw += sum8(q);
        }
        Swp[w][m] = pw;
    }

    if ((int)blockIdx.y < nbig) {
        // ================= BIG: 128n x 128m, TN=8 =================
        const int n0 = blockIdx.y * BNB;
        {
            const int n = tid & 127;
            const int w = tid >> 7;
            float px = 0.f;
            #pragma unroll
            for (int i = 0; i < 2; i++) {
                int dc = w + 4 * i;
                float4 v0 = x4[(size_t)(n0 + n) * 16 + dc * 2];
                float4 v1 = x4[(size_t)(n0 + n) * 16 + dc * 2 + 1];
                h2quad q = cvt2(v0, v1);
                xs[dc][n] = q;
                px += sum8(q);
            }
            Sxp[w][n] = px;
        }
        __syncthreads();

        float facc[8][4];
        #pragma unroll
        for (int i = 0; i < 8; i++)
            #pragma unroll
            for (int j = 0; j < 4; j++) facc[i][j] = 0.f;

        #pragma unroll
        for (int g = 0; g < 2; g++) {
            __half2 hacc[8][4];
            #pragma unroll
            for (int h = 0; h < 4; h++) {
                const int dc = g * 4 + h;
                h2quad xr[8], wr[4];
                #pragma unroll
                for (int i = 0; i < 8; i++) xr[i] = xs[dc][ty * 8 + i];   // warp-uniform bcast
                #pragma unroll
                for (int j = 0; j < 4; j++) wr[j] = ws[dc][j * 32 + tx];  // conflict-free
                #pragma unroll
                for (int i = 0; i < 8; i++)
                    #pragma unroll
                    for (int j = 0; j < 4; j++) {
                        __half2 t0 = __hmax2(xr[i].a, wr[j].a);
                        __half2 t1 = __hmax2(xr[i].b, wr[j].b);
                        __half2 t2 = __hmax2(xr[i].c, wr[j].c);
                        __half2 t3 = __hmax2(xr[i].d, wr[j].d);
                        __half2 s  = __hadd2(__hadd2(t0, t1), __hadd2(t2, t3));
                        if (h == 0) hacc[i][j] = s;
                        else        hacc[i][j] = __hadd2(hacc[i][j], s);
                    }
            }
            #pragma unroll
            for (int i = 0; i < 8; i++)
                #pragma unroll
                for (int j = 0; j < 4; j++) {
                    float2 f = __half22float2(hacc[i][j]);
                    ffma_acc1(facc[i][j], f.x);
                    ffma_acc1(facc[i][j], f.y);
                }
        }

        float sxr[8], swr[4];
        #pragma unroll
        for (int i = 0; i < 8; i++) {
            int n = ty * 8 + i;
            sxr[i] = (Sxp[0][n] + Sxp[1][n]) + (Sxp[2][n] + Sxp[3][n]);
        }
        #pragma unroll
        for (int j = 0; j < 4; j++) {
            int m = j * 32 + tx;
            swr[j] = (Swp[0][m] + Swp[1][m]) + (Swp[2][m] + Swp[3][m]);
        }
        #pragma unroll
        for (int i = 0; i < 8; i++) {
            const size_t nrow = (size_t)(n0 + ty * 8 + i) * (size_t)Mtot;
            #pragma unroll
            for (int j = 0; j < 4; j++)
                out[nrow + m0 + j * 32 + tx] = fmaf(-2.f, facc[i][j], sxr[i] + swr[j]);
        }
    } else {
        // ================= SMALL: 64n x 128m, TN=4 =================
        const int n0 = nbig * BNB + (blockIdx.y - nbig) * 64;
        {
            const int n  = tid & 63;
            const int dc = tid >> 6;     // 0..7, 1 item/thread
            float4 v0 = x4[(size_t)(n0 + n) * 16 + dc * 2];
            float4 v1 = x4[(size_t)(n0 + n) * 16 + dc * 2 + 1];
            h2quad q = cvt2(v0, v1);
            xs[dc][n] = q;
            Sxp[dc & 3][n + (dc >> 2) * 64] = sum8(q);
        }
        __syncthreads();

        float facc[4][4];
        #pragma unroll
        for (int i = 0; i < 4; i++)
            #pragma unroll
            for (int j = 0; j < 4; j++) facc[i][j] = 0.f;

        #pragma unroll
        for (int g = 0; g < 2; g++) {
            __half2 hacc[4][4];
            #pragma unroll
            for (int h = 0; h < 4; h++) {
                const int dc = g * 4 + h;
                h2quad xr[4], wr[4];
                #pragma unroll
                for (int i = 0; i < 4; i++) xr[i] = xs[dc][ty * 4 + i];   // warp-uniform
                #pragma unroll
                for (int j = 0; j < 4; j++) wr[j] = ws[dc][j * 32 + tx];
                #pragma unroll
                for (int i = 0; i < 4; i++)
                    #pragma unroll
                    for (int j = 0; j < 4; j++) {
                        __half2 t0 = __hmax2(xr[i].a, wr[j].a);
                        __half2 t1 = __hmax2(xr[i].b, wr[j].b);
                        __half2 t2 = __hmax2(xr[i].c, wr[j].c);
                        __half2 t3 = __hmax2(xr[i].d, wr[j].d);
                        __half2 s  = __hadd2(__hadd2(t0, t1), __hadd2(t2, t3));
                        if (h == 0) hacc[i][j] = s;
                        else        hacc[i][j] = __hadd2(hacc[i][j], s);
                    }
            }
            #pragma unroll
            for (int i = 0; i < 4; i++)
                #pragma unroll
                for (int j = 0; j < 4; j++) {
                    float2 f = __half22float2(hacc[i][j]);
                    ffma_acc1(facc[i][j], f.x);
                    ffma_acc1(facc[i][j], f.y);
                }
        }

        float sxr[4], swr[4];
        #pragma unroll
        for (int i = 0; i < 4; i++) {
            int n = ty * 4 + i;
            sxr[i] = ((Sxp[0][n] + Sxp[0][n + 64]) + (Sxp[1][n] + Sxp[1][n + 64]))
                   + ((Sxp[2][n] + Sxp[2][n + 64]) + (Sxp[3][n] + Sxp[3][n + 64]));
        }
        #pragma unroll
        for (int j = 0; j < 4; j++) {
            int m = j * 32 + tx;
            swr[j] = (Swp[0][m] + Swp[1][m]) + (Swp[2][m] + Swp[3][m]);
        }
        #pragma unroll
        for (int i = 0; i < 4; i++) {
            const size_t nrow = (size_t)(n0 + ty * 4 + i) * (size_t)Mtot;
            #pragma unroll
            for (int j = 0; j < 4; j++)
                out[nrow + m0 + j * 32 + tx] = fmaf(-2.f, facc[i][j], sxr[i] + swr[j]);
        }
    }
}

extern "C" void kernel_launch(void* const* d_in, const int* in_sizes, int n_in,
                              void* d_out, int out_size) {
    const float4* x4 = (const float4*)d_in[0];   // [N, 64] fp32
    const float4* w4 = (const float4*)d_in[1];   // [M, 64] fp32
    float* out = (float*)d_out;                  // [N, M] fp32

    const int N = in_sizes[0] / DD;   // 8192
    const int M = in_sizes[1] / DD;   // 1024

    // mixed n-tiling: 54 big (128-row) + 20 small (64-row) tiles = 74 y-blocks
    int nbig, nsmall;
    if (N == 8192) { nbig = 54; nsmall = 20; }
    else { nbig = N / 128; nsmall = (N - nbig * 128) / 64; }

    dim3 grid(M / BM, nbig + nsmall);   // (8, 74) = 592 blocks, occ1
    cdist_l1_kernel<<<grid, THREADS>>>(x4, w4, out, M, nbig);
}

// round 17
// speedup vs baseline: 1.1033x; 1.1033x over previous
#include <cuda_runtime.h>
#include <cuda_fp16.h>

#define BM 128    // m cols per block
#define DD 64
#define NDC 8     // double-chunks (8 dims = 16B)
#define THREADS 256
#define BNB 64    // big tile rows
#define BNS 32    // small tile rows

struct __align__(16) h2quad { __half2 a, b, c, d; };

__device__ __forceinline__ void ffma_acc1(float &acc, float v) {
    asm("fma.rn.f32 %0, %1, 0f3F800000, %0;" : "+f"(acc) : "f"(v));
}

__device__ __forceinline__ float sum8(const h2quad &q) {
    float2 fa = __half22float2(q.a), fb = __half22float2(q.b);
    float2 fc = __half22float2(q.c), fd = __half22float2(q.d);
    return ((fa.x + fa.y) + (fb.x + fb.y)) + ((fc.x + fc.y) + (fd.x + fd.y));
}

__device__ __forceinline__ h2quad cvt2(const float4 &v0, const float4 &v1) {
    h2quad q;
    q.a = __floats2half2_rn(v0.x, v0.y);
    q.b = __floats2half2_rn(v0.z, v0.w);
    q.c = __floats2half2_rn(v1.x, v1.y);
    q.d = __floats2half2_rn(v1.z, v1.w);
    return q;
}

__global__ __launch_bounds__(THREADS, 2)
void cdist_l1_kernel(const float4* __restrict__ x4,
                     const float4* __restrict__ w4,
                     float* __restrict__ out,
                     int Mtot, int nbig)
{
    __shared__ h2quad xs[NDC][BNB];   // 8KB
    __shared__ h2quad ws[NDC][BM];    // 16KB
    __shared__ float Sxp[4][BNB];
    __shared__ float Swp[2][BM];

    const int tid = threadIdx.x;
    const int m0 = blockIdx.x * BM;
    const int tx = tid & 31;   // m: j*32 + tx  (coalesced 128B)
    const int ty = tid >> 5;   // warp id; n: ty*8+i (big) / ty*4+i (small)

    // ---- w tile: 128 rows x 8 dc = 1024 items, 4/thread ----
    {
        const int m = tid & 127;
        const int w = tid >> 7;          // 0..1
        float pw = 0.f;
        #pragma unroll
        for (int i = 0; i < 4; i++) {
            int dc = w + 2 * i;
            float4 v0 = w4[(size_t)(m0 + m) * 16 + dc * 2];
            float4 v1 = w4[(size_t)(m0 + m) * 16 + dc * 2 + 1];
            h2quad q = cvt2(v0, v1);
            ws[dc][m] = q;
            pw += sum8(q);
        }
        Swp[w][m] = pw;
    }

    if ((int)blockIdx.y < nbig) {
        // ================= BIG: 64n x 128m, TN=8 =================
        const int n0 = blockIdx.y * BNB;
        {
            const int n = tid & 63;
            const int w = tid >> 6;      // 0..3
            float px = 0.f;
            #pragma unroll
            for (int i = 0; i < 2; i++) {
                int dc = w + 4 * i;
                float4 v0 = x4[(size_t)(n0 + n) * 16 + dc * 2];
                float4 v1 = x4[(size_t)(n0 + n) * 16 + dc * 2 + 1];
                h2quad q = cvt2(v0, v1);
                xs[dc][n] = q;
                px += sum8(q);
            }
            Sxp[w][n] = px;
        }
        __syncthreads();

        float facc[8][4];
        #pragma unroll
        for (int i = 0; i < 8; i++)
            #pragma unroll
            for (int j = 0; j < 4; j++) facc[i][j] = 0.f;

        #pragma unroll
        for (int g = 0; g < 2; g++) {
            __half2 hacc[8][4];
            #pragma unroll
            for (int h = 0; h < 4; h++) {
                const int dc = g * 4 + h;
                h2quad xr[8], wr[4];
                #pragma unroll
                for (int i = 0; i < 8; i++) xr[i] = xs[dc][ty * 8 + i];   // warp-uniform
                #pragma unroll
                for (int j = 0; j < 4; j++) wr[j] = ws[dc][j * 32 + tx];  // conflict-free
                #pragma unroll
                for (int i = 0; i < 8; i++)
                    #pragma unroll
                    for (int j = 0; j < 4; j++) {
                        __half2 t0 = __hmax2(xr[i].a, wr[j].a);
                        __half2 t1 = __hmax2(xr[i].b, wr[j].b);
                        __half2 t2 = __hmax2(xr[i].c, wr[j].c);
                        __half2 t3 = __hmax2(xr[i].d, wr[j].d);
                        __half2 s  = __hadd2(__hadd2(t0, t1), __hadd2(t2, t3));
                        if (h == 0) hacc[i][j] = s;
                        else        hacc[i][j] = __hadd2(hacc[i][j], s);
                    }
            }
            #pragma unroll
            for (int i = 0; i < 8; i++)
                #pragma unroll
                for (int j = 0; j < 4; j++) {
                    float2 f = __half22float2(hacc[i][j]);
                    ffma_acc1(facc[i][j], f.x);
                    ffma_acc1(facc[i][j], f.y);
                }
        }

        float sxr[8], swr[4];
        #pragma unroll
        for (int i = 0; i < 8; i++) {
            int n = ty * 8 + i;
            sxr[i] = (Sxp[0][n] + Sxp[1][n]) + (Sxp[2][n] + Sxp[3][n]);
        }
        #pragma unroll
        for (int j = 0; j < 4; j++) {
            int m = j * 32 + tx;
            swr[j] = Swp[0][m] + Swp[1][m];
        }
        #pragma unroll
        for (int i = 0; i < 8; i++) {
            const size_t nrow = (size_t)(n0 + ty * 8 + i) * (size_t)Mtot;
            #pragma unroll
            for (int j = 0; j < 4; j++)
                out[nrow + m0 + j * 32 + tx] = fmaf(-2.f, facc[i][j], sxr[i] + swr[j]);
        }
    } else {
        // ================= SMALL: 32n x 128m, TN=4 =================
        const int n0 = nbig * BNB + (blockIdx.y - nbig) * BNS;
        {
            const int n  = tid & 31;
            const int dc = tid >> 5;     // 0..7, 1 item/thread
            float4 v0 = x4[(size_t)(n0 + n) * 16 + dc * 2];
            float4 v1 = x4[(size_t)(n0 + n) * 16 + dc * 2 + 1];
            h2quad q = cvt2(v0, v1);
            xs[dc][n] = q;
            Sxp[dc & 3][n + (dc >> 2) * 32] = sum8(q);
        }
        __syncthreads();

        float facc[4][4];
        #pragma unroll
        for (int i = 0; i < 4; i++)
            #pragma unroll
            for (int j = 0; j < 4; j++) facc[i][j] = 0.f;

        #pragma unroll
        for (int g = 0; g < 2; g++) {
            __half2 hacc[4][4];
            #pragma unroll
            for (int h = 0; h < 4; h++) {
                const int dc = g * 4 + h;
                h2quad xr[4], wr[4];
                #pragma unroll
                for (int i = 0; i < 4; i++) xr[i] = xs[dc][ty * 4 + i];   // warp-uniform
                #pragma unroll
                for (int j = 0; j < 4; j++) wr[j] = ws[dc][j * 32 + tx];
                #pragma unroll
                for (int i = 0; i < 4; i++)
                    #pragma unroll
                    for (int j = 0; j < 4; j++) {
                        __half2 t0 = __hmax2(xr[i].a, wr[j].a);
                        __half2 t1 = __hmax2(xr[i].b, wr[j].b);
                        __half2 t2 = __hmax2(xr[i].c, wr[j].c);
                        __half2 t3 = __hmax2(xr[i].d, wr[j].d);
                        __half2 s  = __hadd2(__hadd2(t0, t1), __hadd2(t2, t3));
                        if (h == 0) hacc[i][j] = s;
                        else        hacc[i][j] = __hadd2(hacc[i][j], s);
                    }
            }
            #pragma unroll
            for (int i = 0; i < 4; i++)
                #pragma unroll
                for (int j = 0; j < 4; j++) {
                    float2 f = __half22float2(hacc[i][j]);
                    ffma_acc1(facc[i][j], f.x);
                    ffma_acc1(facc[i][j], f.y);
                }
        }

        float sxr[4], swr[4];
        #pragma unroll
        for (int i = 0; i < 4; i++) {
            int n = ty * 4 + i;
            sxr[i] = ((Sxp[0][n] + Sxp[0][n + 32]) + (Sxp[1][n] + Sxp[1][n + 32]))
                   + ((Sxp[2][n] + Sxp[2][n + 32]) + (Sxp[3][n] + Sxp[3][n + 32]));
        }
        #pragma unroll
        for (int j = 0; j < 4; j++) {
            int m = j * 32 + tx;
            swr[j] = Swp[0][m] + Swp[1][m];
        }
        #pragma unroll
        for (int i = 0; i < 4; i++) {
            const size_t nrow = (size_t)(n0 + ty * 4 + i) * (size_t)Mtot;
            #pragma unroll
            for (int j = 0; j < 4; j++)
                out[nrow + m0 + j * 32 + tx] = fmaf(-2.f, facc[i][j], sxr[i] + swr[j]);
        }
    }
}

extern "C" void kernel_launch(void* const* d_in, const int* in_sizes, int n_in,
                              void* d_out, int out_size) {
    const float4* x4 = (const float4*)d_in[0];   // [N, 64] fp32
    const float4* w4 = (const float4*)d_in[1];   // [M, 64] fp32
    float* out = (float*)d_out;                  // [N, M] fp32

    const int N = in_sizes[0] / DD;   // 8192
    const int M = in_sizes[1] / DD;   // 1024

    // mixed n-tiling: 108 big (64-row) + 40 small (32-row) = 148 y-blocks
    // grid = 8 x 148 = 1184 blocks = 296 * 4 exact occ-2 waves
    int nbig, nsmall;
    if (N == 8192) { nbig = 108; nsmall = 40; }
    else { nbig = N / BNB; nsmall = (N - nbig * BNB) / BNS; }

    dim3 grid(M / BM, nbig + nsmall);
    cdist_l1_kernel<<<grid, THREADS>>>(x4, w4, out, M, nbig);
}